// round 15
// baseline (speedup 1.0000x reference)
#include <cuda_runtime.h>
#include <cuda_fp16.h>
#include <math.h>

#define NN   50000
#define EE   800000
#define ET   (EE + NN)        // edges + self loops
#define FIN  128
#define HID  64
#define NEG_SLOPE 0.2f

#define SCAN_B   256
#define SCAN_G   ((NN + SCAN_B - 1) / SCAN_B)   // 196
#define NWARPS   (SCAN_B / 32)                  // 8
#define SCAN_T   (SCAN_G * SCAN_B)              // total scan threads

#define GR   128              // gemm rows per block
#define KCH  32               // gemm k-chunk per phase
#define XPAD 4                // row padding for transpose store

// ---------------- scratch (device globals; no allocs allowed) ----------------
__device__ __align__(16) __half g_hh[NN * HID];  // x @ W in fp16 (sole consumer: aggregate)
__device__ float g_asrc[NN];
__device__ float g_adst[NN];
__device__ int   g_count[NN];          // degree histogram (zero at entry; restored by aggregate)
__device__ int   g_cursor[NN];         // scatter cursors
__device__ int   g_offsets[NN + 1];    // CSR offsets
__device__ int   g_srcs[ET];           // src node per CSR slot
__device__ int2  g_sd[EE];             // packed (src,dst) int32
__device__ float g_s0[NN];
__device__ float g_s1[NN];
__device__ int   g_bsum[SCAN_G];       // per-block count sums
__device__ int   g_barrier;            // scan spin barrier (reset by edges each launch)

// packed fp32x2 helpers (Blackwell)
__device__ __forceinline__ unsigned long long fma2(unsigned long long a,
                                                   unsigned long long b,
                                                   unsigned long long c) {
    unsigned long long d;
    asm("fma.rn.f32x2 %0, %1, %2, %3;" : "=l"(d) : "l"(a), "l"(b), "l"(c));
    return d;
}
__device__ __forceinline__ unsigned long long pack2(float lo, float hi) {
    unsigned long long r;
    asm("mov.b64 %0, {%1, %2};" : "=l"(r) : "f"(lo), "f"(hi));
    return r;
}
__device__ __forceinline__ float2 unpack2(unsigned long long v) {
    float2 r;
    asm("mov.b64 {%0, %1}, %2;" : "=f"(r.x), "=f"(r.y) : "l"(v));
    return r;
}

// ---------------- GEMM (f32x2) + fp16 h store + attn epilogue ----------------
__global__ void gemm_kernel(const float* __restrict__ x, const float* __restrict__ W,
                            const float* __restrict__ att_src, const float* __restrict__ att_dst) {
    __shared__ float xsT[KCH][GR + XPAD];   // [k][row]  ~16.5KB
    __shared__ float Ws[KCH][HID];          // [k][col]   8KB

    const int tid  = threadIdx.x;
    const int row0 = blockIdx.x * GR;
    const int tr   = tid >> 3;   // 0..15
    const int tc   = tid & 7;    // 0..7

    unsigned long long acc[8][4];
    #pragma unroll
    for (int i = 0; i < 8; i++)
        #pragma unroll
        for (int j = 0; j < 4; j++) acc[i][j] = 0ull;

    #pragma unroll
    for (int ph = 0; ph < FIN / KCH; ph++) {
        #pragma unroll
        for (int it = 0; it < 8; it++) {
            int f  = it * 128 + tid;
            int r  = f >> 3;
            int k4 = f & 7;
            float4 v = make_float4(0.f, 0.f, 0.f, 0.f);
            if (row0 + r < NN)
                v = *(const float4*)&x[(long long)(row0 + r) * FIN + ph * KCH + k4 * 4];
            xsT[k4 * 4 + 0][r] = v.x;
            xsT[k4 * 4 + 1][r] = v.y;
            xsT[k4 * 4 + 2][r] = v.z;
            xsT[k4 * 4 + 3][r] = v.w;
        }
        #pragma unroll
        for (int it = 0; it < 4; it++) {
            int f  = it * 128 + tid;
            int kk = f >> 4;
            int c4 = f & 15;
            *(float4*)&Ws[kk][c4 * 4] = *(const float4*)&W[(ph * KCH + kk) * HID + c4 * 4];
        }
        __syncthreads();

        #pragma unroll 4
        for (int k = 0; k < KCH; k++) {
            float4 a0 = *(const float4*)&xsT[k][tr * 8];
            float4 a1 = *(const float4*)&xsT[k][tr * 8 + 4];
            const unsigned long long* bp = (const unsigned long long*)&Ws[k][tc * 8];
            unsigned long long b0 = bp[0], b1 = bp[1], b2 = bp[2], b3 = bp[3];
            float a[8] = {a0.x, a0.y, a0.z, a0.w, a1.x, a1.y, a1.z, a1.w};
            #pragma unroll
            for (int i = 0; i < 8; i++) {
                unsigned long long ai = pack2(a[i], a[i]);
                acc[i][0] = fma2(ai, b0, acc[i][0]);
                acc[i][1] = fma2(ai, b1, acc[i][1]);
                acc[i][2] = fma2(ai, b2, acc[i][2]);
                acc[i][3] = fma2(ai, b3, acc[i][3]);
            }
        }
        __syncthreads();
    }

    float as[8], ad[8];
    #pragma unroll
    for (int j = 0; j < 8; j++) { as[j] = att_src[tc * 8 + j]; ad[j] = att_dst[tc * 8 + j]; }

    float* redA = (float*)xsT;           // [128][8]
    float* redB = redA + GR * 8;         // [128][8]

    #pragma unroll
    for (int i = 0; i < 8; i++) {
        int row = tr * 8 + i;
        int r   = row0 + row;
        float2 c0 = unpack2(acc[i][0]);
        float2 c1 = unpack2(acc[i][1]);
        float2 c2 = unpack2(acc[i][2]);
        float2 c3 = unpack2(acc[i][3]);
        if (r < NN) {
            __half2 p0 = __floats2half2_rn(c0.x, c0.y);
            __half2 p1 = __floats2half2_rn(c1.x, c1.y);
            __half2 p2 = __floats2half2_rn(c2.x, c2.y);
            __half2 p3 = __floats2half2_rn(c3.x, c3.y);
            uint4 pv;
            pv.x = *(const unsigned*)&p0;
            pv.y = *(const unsigned*)&p1;
            pv.z = *(const unsigned*)&p2;
            pv.w = *(const unsigned*)&p3;
            *(uint4*)&g_hh[(long long)r * HID + tc * 8] = pv;   // 8 cols as fp16
        }
        float pa = c0.x * as[0] + c0.y * as[1] + c1.x * as[2] + c1.y * as[3]
                 + c2.x * as[4] + c2.y * as[5] + c3.x * as[6] + c3.y * as[7];
        float pb = c0.x * ad[0] + c0.y * ad[1] + c1.x * ad[2] + c1.y * ad[3]
                 + c2.x * ad[4] + c2.y * ad[5] + c3.x * ad[6] + c3.y * ad[7];
        redA[row * 8 + tc] = pa;
        redB[row * 8 + tc] = pb;
    }
    __syncthreads();
    {
        int r = row0 + tid;
        if (r < NN) {
            float sa = 0.f, sb = 0.f;
            #pragma unroll
            for (int j = 0; j < 8; j++) { sa += redA[tid * 8 + j]; sb += redB[tid * 8 + j]; }
            g_asrc[r] = sa;
            g_adst[r] = sb;
        }
    }
}

// ---------------- edges: detect + packed conversion + dst histogram (2 edges/thread) ----
__global__ void edges_kernel(const void* ei) {
    __shared__ int sIs64;
    int t  = blockIdx.x * blockDim.x + threadIdx.x;
    if (threadIdx.x == 0) {
        if (blockIdx.x == 0) g_barrier = 0;      // reset for this launch's scan
        const int* ew = (const int*)ei;
        int all0 = 1;
        #pragma unroll 8
        for (int j = 0; j < 64; j++) {
            if (ew[2 * j + 1] != 0) { all0 = 0; break; }
        }
        sIs64 = all0;
    }
    __syncthreads();
    int is64 = sIs64;

    int i0 = t * 2;
    if (i0 >= EE) return;
    int s0, d0, s1, d1;
    if (is64) {
        longlong2 sv = *(const longlong2*)((const long long*)ei + i0);
        longlong2 dv = *(const longlong2*)((const long long*)ei + EE + i0);
        s0 = (int)sv.x; s1 = (int)sv.y;
        d0 = (int)dv.x; d1 = (int)dv.y;
    } else {
        int2 sv = *(const int2*)((const int*)ei + i0);
        int2 dv = *(const int2*)((const int*)ei + EE + i0);
        s0 = sv.x; s1 = sv.y;
        d0 = dv.x; d1 = dv.y;
    }
    g_sd[i0] = make_int2(s0, d0);
    atomicAdd(&g_count[d0], 1);
    if (i0 + 1 < EE) {
        g_sd[i0 + 1] = make_int2(s1, d1);
        atomicAdd(&g_count[d1], 1);
    }
}

// ---------------- scan + scatter in one kernel (two spin barriers) ----------------
// 196 blocks, all resident in wave 1 -> spins are deadlock-free.
__global__ void scan_scatter_kernel() {
    __shared__ int wsum[NWARPS];
    __shared__ int wpre[NWARPS];
    __shared__ int sTot;
    __shared__ int bsc[SCAN_B];

    int t    = threadIdx.x;
    int bid  = blockIdx.x;
    int i    = bid * SCAN_B + t;
    int lane = t & 31;
    int warp = t >> 5;

    // phase A: local scan (counts are zero-based; +1 = self loop)
    int c = (i < NN) ? g_count[i] + 1 : 0;
    int v = c;
    #pragma unroll
    for (int o = 1; o < 32; o <<= 1) {
        int u = __shfl_up_sync(0xffffffffu, v, o);
        if (lane >= o) v += u;
    }
    if (lane == 31) wsum[warp] = v;
    __syncthreads();
    if (warp == 0) {
        int u = (lane < NWARPS) ? wsum[lane] : 0;
        int s = u;
        #pragma unroll
        for (int o = 1; o < 32; o <<= 1) {
            int t2 = __shfl_up_sync(0xffffffffu, s, o);
            if (lane >= o) s += t2;
        }
        if (lane < NWARPS) wpre[lane] = s - u;
        if (lane == NWARPS - 1) sTot = s;
    }
    __syncthreads();

    // barrier 1: all block sums published
    if (t == 0) {
        g_bsum[bid] = sTot;
        __threadfence();
        atomicAdd(&g_barrier, 1);
        while (atomicAdd(&g_barrier, 0) < SCAN_G) { }
        __threadfence();
    }
    __syncthreads();

    // phase B: scan block sums (redundant per block), write offsets + cursors
    int bv = (t < SCAN_G) ? g_bsum[t] : 0;
    bsc[t] = bv;
    __syncthreads();
    for (int off = 1; off < SCAN_B; off <<= 1) {
        int add = (t >= off) ? bsc[t - off] : 0;
        __syncthreads();
        bsc[t] += add;
        __syncthreads();
    }
    int blockPre = (bid == 0) ? 0 : bsc[bid - 1];
    if (bid == 0 && t == 0) g_offsets[NN] = ET;
    if (i < NN) {
        int off = blockPre + wpre[warp] + (v - c);   // exclusive
        g_offsets[i] = off;
        g_cursor[i]  = off;
    }

    // barrier 2: all cursors written
    if (t == 0) {
        __threadfence();
        atomicAdd(&g_barrier, 1);
        while (atomicAdd(&g_barrier, 0) < 2 * SCAN_G) { }
        __threadfence();
    }
    __syncthreads();

    // phase C: position scatter (grid-strided over all edges + self loops)
    for (int e = bid * SCAN_B + t; e < ET; e += SCAN_T) {
        int s, d;
        if (e < EE) { int2 sd = g_sd[e]; s = sd.x; d = sd.y; }
        else        { s = d = e - EE; }
        int pos = atomicAdd(&g_cursor[d], 1);
        g_srcs[pos] = s;
    }
}

// ---------------- aggregate: in-kernel weights + fp16 h + ELU + fc fold ----------------
// warp per dst node; lanes batch-load 32 (src, weight) then shuffle-broadcast;
// full warp gathers the 64-col fp16 row (half2 per lane).
__global__ void aggregate_kernel(const float* __restrict__ bias,
                                 const float* __restrict__ fcw,
                                 const float* __restrict__ fcb) {
    int n    = (blockIdx.x * blockDim.x + threadIdx.x) >> 5;
    int lane = threadIdx.x & 31;
    if (n >= NN) return;

    int start = g_offsets[n];
    int end   = g_offsets[n + 1];
    float adst = g_adst[n];

    float2 acc = make_float2(0.f, 0.f);      // lane owns cols 2*lane, 2*lane+1
    float wsum = 0.f;

    for (int base = start; base < end; base += 32) {
        int idx = base + lane;
        int s = 0; float w = 0.f;
        if (idx < end) {
            s = g_srcs[idx];
            float e = g_asrc[s] + adst;
            e = (e > 0.f) ? e : NEG_SLOPE * e;
            w = __expf(e);
        }
        wsum += w;
        int m = end - base; if (m > 32) m = 32;
        for (int j = 0; j < m; j++) {
            int   sj = __shfl_sync(0xffffffffu, s, j);
            float wj = __shfl_sync(0xffffffffu, w, j);
            unsigned hv = *(const unsigned*)&g_hh[(long long)sj * HID + lane * 2];
            float2 f = __half22float2(*(const __half2*)&hv);
            acc.x = fmaf(wj, f.x, acc.x);
            acc.y = fmaf(wj, f.y, acc.y);
        }
    }

    #pragma unroll
    for (int o = 16; o; o >>= 1) wsum += __shfl_xor_sync(0xffffffffu, wsum, o);

    float inv = 1.0f / wsum;
    float2 b  = *(const float2*)&bias[lane * 2];
    float o0 = acc.x * inv + b.x;
    float o1 = acc.y * inv + b.y;
    o0 = (o0 > 0.f) ? o0 : expm1f(o0);
    o1 = (o1 > 0.f) ? o1 : expm1f(o1);

    float2 f0 = *(const float2*)&fcw[lane * 2];
    float2 f1 = *(const float2*)&fcw[HID + lane * 2];
    float p0 = o0 * f0.x + o1 * f0.y;
    float p1 = o0 * f1.x + o1 * f1.y;
    #pragma unroll
    for (int o = 16; o; o >>= 1) {
        p0 += __shfl_xor_sync(0xffffffffu, p0, o);
        p1 += __shfl_xor_sync(0xffffffffu, p1, o);
    }
    if (lane == 0) {
        g_s0[n] = p0 + fcb[0];   // fold fc bias into s0
        g_s1[n] = p1;
        g_count[n] = 0;          // restore zero-count invariant for next launch
    }
}

// ---------------- per-edge scores (4 edges per thread, packed pairs) ----------------
__global__ void score_kernel(float* __restrict__ out) {
    int t = blockIdx.x * blockDim.x + threadIdx.x;
    int e0 = t * 4;
    if (e0 >= EE) return;
    if (e0 + 4 <= EE) {
        int4 p01 = *(const int4*)&g_sd[e0];       // (s0,d0,s1,d1)
        int4 p23 = *(const int4*)&g_sd[e0 + 2];   // (s2,d2,s3,d3)
        float4 r;
        r.x = g_s0[p01.x] + g_s1[p01.y];
        r.y = g_s0[p01.z] + g_s1[p01.w];
        r.z = g_s0[p23.x] + g_s1[p23.y];
        r.w = g_s0[p23.z] + g_s1[p23.w];
        *(float4*)&out[e0] = r;
    } else {
        for (int e = e0; e < EE; e++) {
            int2 sd = g_sd[e];
            out[e] = g_s0[sd.x] + g_s1[sd.y];
        }
    }
}

// ---------------- launch: gemm overlaps the ENTIRE edge pipeline (incl. scatter) ----
extern "C" void kernel_launch(void* const* d_in, const int* in_sizes, int n_in,
                              void* d_out, int out_size) {
    const float* x   = (const float*)d_in[0];
    const void*  ei  = d_in[1];
    const float* W   = (const float*)d_in[2];
    const float* asv = (const float*)d_in[3];
    const float* adv = (const float*)d_in[4];
    const float* bias= (const float*)d_in[5];
    const float* fcw = (const float*)d_in[6];
    const float* fcb = (const float*)d_in[7];
    float* out = (float*)d_out;

    // one-time host-side stream/event setup (no device allocations)
    static cudaStream_t s2 = nullptr;
    static cudaEvent_t evFork = nullptr, evJoin = nullptr;
    if (s2 == nullptr) {
        cudaStreamCreateWithFlags(&s2, cudaStreamNonBlocking);
        cudaEventCreateWithFlags(&evFork, cudaEventDisableTiming);
        cudaEventCreateWithFlags(&evJoin, cudaEventDisableTiming);
    }

    // fork: gemm independent of the whole edge pipeline now
    cudaEventRecord(evFork, 0);
    cudaStreamWaitEvent(s2, evFork, 0);
    gemm_kernel<<<(NN + GR - 1) / GR, 128, 0, s2>>>(x, W, asv, adv);

    // edge branch: convert+hist, then fused scan+scatter
    edges_kernel<<<(EE / 2 + 255) / 256, 256>>>(ei);
    scan_scatter_kernel<<<SCAN_G, SCAN_B>>>();

    // join: aggregate needs gemm (h, asrc, adst) and the CSR
    cudaEventRecord(evJoin, s2);
    cudaStreamWaitEvent(0, evJoin, 0);

    aggregate_kernel<<<(NN * 32 + 255) / 256, 256>>>(bias, fcw, fcb);
    score_kernel<<<(EE / 4 + 255) / 256, 256>>>(out);
}